// round 15
// baseline (speedup 1.0000x reference)
#include <cuda_runtime.h>
#include <cuda_fp16.h>
#include <cstdint>
#include <math.h>

#define NTOK 4096
#define HDIM 1024
#define NEXP 16
#define IDIM 512
#define ISH  2048
#define TOPK 4

#define RS        40                       // halves per smem row stride (80 bytes)
#define STAGE_B   (384 * RS * 2)           // 30720 bytes per stage (384 rows)
#define NSTAGE    4
#define GEMM_SMEM (NSTAGE * STAGE_B)       // 122880 bytes

// ---------------- fp16 operand copies + scratch (device globals) ----------------
__device__ __align__(16) __half g_h16[(size_t)NTOK * HDIM];
__device__ __align__(16) __half g_gup16[(size_t)NEXP * 2 * IDIM * HDIM];
__device__ __align__(16) __half g_dwn16[(size_t)NEXP * HDIM * IDIM];
__device__ __align__(16) __half g_sgw16[(size_t)ISH * HDIM];
__device__ __align__(16) __half g_suw16[(size_t)ISH * HDIM];
__device__ __align__(16) __half g_sdw16[(size_t)HDIM * ISH];
__device__ __align__(16) __half g_sact16[(size_t)NTOK * ISH];
__device__ __align__(16) __half g_eact16[(size_t)NTOK * TOPK * IDIM];
__device__ int   g_list[NEXP * NTOK];
__device__ float g_topw[NTOK * TOPK];
__device__ float g_gatesc[NTOK];

struct SyncBlk {
    int rtr;           // router blocks done (target RTRB)
    int h_c;           // h cvt blocks done (64)
    int sh_c;          // sgw+suw cvt blocks done (64)
    int sdw_c;         // sdw cvt blocks (32)
    int out_c;         // out-zero blocks (64)
    int gup_c[NEXP];   // per-expert gup cvt blocks (32)
    int dwn_c[NEXP];   // per-expert dwn cvt blocks (8)
    int cnt[NEXP];     // tokens per expert (router)
    int rdy_e[NEXP];   // dual-expert blocks done per expert (128)
    int rdy_s[32];     // dual-shared blocks done per row chunk (16)
};
__device__ SyncBlk g_sync;

// sizes (in float4 units)
#define N4_H      ((size_t)NTOK * HDIM / 4)            // 1048576
#define N4_SGW    ((size_t)ISH * HDIM / 4)             // 524288
#define N4_GUP_E  ((size_t)2 * IDIM * HDIM / 4)        // 262144
#define N4_DWN_E  ((size_t)HDIM * IDIM / 4)            // 131072
#define N4_SDW    ((size_t)HDIM * ISH / 4)             // 524288
#define N4_OUT    ((size_t)NTOK * HDIM / 4)            // 1048576

#define RTRB      512
#define CVTB      864          // 64 h + 64 sh + 512 gup + 128 dwn + 32 sdw + 64 outz

// ---------------- helpers ----------------
__device__ __forceinline__ uint32_t smem_u32(const void* p) {
    uint32_t a;
    asm("{ .reg .u64 t; cvta.to.shared.u64 t, %1; cvt.u32.u64 %0, t; }" : "=r"(a) : "l"(p));
    return a;
}
__device__ __forceinline__ void ldm4(uint32_t* r, uint32_t addr) {
    asm volatile("ldmatrix.sync.aligned.m8n8.x4.shared.b16 {%0,%1,%2,%3}, [%4];"
                 : "=r"(r[0]), "=r"(r[1]), "=r"(r[2]), "=r"(r[3]) : "r"(addr));
}
__device__ __forceinline__ void mma16(float* d, const uint32_t* a, uint32_t b0, uint32_t b1) {
    asm volatile(
        "mma.sync.aligned.m16n8k16.row.col.f32.f16.f16.f32 "
        "{%0,%1,%2,%3}, {%4,%5,%6,%7}, {%8,%9}, {%0,%1,%2,%3};"
        : "+f"(d[0]), "+f"(d[1]), "+f"(d[2]), "+f"(d[3])
        : "r"(a[0]), "r"(a[1]), "r"(a[2]), "r"(a[3]), "r"(b0), "r"(b1));
}
__device__ __forceinline__ void cp16(uint32_t dst, const void* src) {
    asm volatile("cp.async.cg.shared.global [%0], [%1], 16;" :: "r"(dst), "l"(src));
}
#define CP_COMMIT() asm volatile("cp.async.commit_group;" ::: "memory")
#define CP_WAIT2()  asm volatile("cp.async.wait_group 2;" ::: "memory")
__device__ __forceinline__ float silu_mul(float g, float u) {
    return g / (1.f + expf(-g)) * u;
}
__device__ __forceinline__ void red4(float* p, float a, float b, float cc, float dd) {
    asm volatile("red.global.add.v4.f32 [%0], {%1,%2,%3,%4};"
                 :: "l"(p), "f"(a), "f"(b), "f"(cc), "f"(dd) : "memory");
}
__device__ __forceinline__ int ld_acq(const int* p) {
    int v;
    asm volatile("ld.global.acquire.gpu.b32 %0, [%1];" : "=r"(v) : "l"(p) : "memory");
    return v;
}
#define SPIN(ptr, tgt) while (ld_acq(ptr) < (tgt)) { }
#define SIGNAL(ptr) do { __syncthreads(); if (tid == 0) { __threadfence(); atomicAdd((ptr), 1); } } while (0)

__device__ __forceinline__ void cvt_seg(const float4* __restrict__ src, __half2* __restrict__ dst,
                                        size_t n4, int idx, int nblk, int tid) {
    size_t stride = (size_t)nblk * 512;
    for (size_t j = (size_t)idx * 512 + tid; j < n4; j += stride) {
        float4 v = src[j];
        dst[2 * j]     = __floats2half2_rn(v.x, v.y);
        dst[2 * j + 1] = __floats2half2_rn(v.z, v.w);
    }
}

// stage fill: threads 0..383 each own one row; 64 bytes per stage
#define LOADSTAGE(st, k0)                                              \
    do {                                                               \
        if (tid < 384) {                                               \
            uint32_t _d = sb + (uint32_t)(st) * STAGE_B + (uint32_t)tid * (RS * 2); \
            const __half* _s = mySrc + (k0);                           \
            cp16(_d, _s); cp16(_d + 16, _s + 8);                       \
            cp16(_d + 32, _s + 16); cp16(_d + 48, _s + 24);            \
        }                                                              \
    } while (0)

// =====================================================================
// THE kernel. Bid layout (strictly producer-before-consumer):
//   [0, RTRB)                 router (8 tokens each)
//   [RTRB, RTRB+CVTB)         fp32->fp16 conversion segments + out zero
//   [DUAL_BASE, +DUAL_TOT)    dual gate/up GEMMs (spin on cvt/router)
//   [SGL_BASE, +SGL_TOT)      single down-proj GEMMs (spin on rdy flags)
// =====================================================================

#define DUAL_SH_BLKS  ((ISH / 128) * (NTOK / 128))                // 512
#define DUAL_EX_BLKS  ((IDIM / 128) * (NTOK / 128) * NEXP)        // 2048
#define DUAL_TOT      (DUAL_SH_BLKS + DUAL_EX_BLKS)               // 2560
#define SGL_SH_BLKS   ((HDIM / 256) * (NTOK / 128))               // 128
#define SGL_EX_BLKS   ((HDIM / 256) * (NTOK / 128) * NEXP)        // 2048
#define SGL_TOT       (SGL_SH_BLKS + SGL_EX_BLKS)                 // 2176
#define DUAL_BASE     (RTRB + CVTB)                               // 1376
#define SGL_BASE      (DUAL_BASE + DUAL_TOT)                      // 3936
#define GRID_TOT      (SGL_BASE + SGL_TOT)                        // 6112

__global__ void __launch_bounds__(512, 1) k_all(
        const float*  __restrict__ hf,   const float* __restrict__ rw,
        const float*  __restrict__ egw,
        const float4* __restrict__ h4,   const float4* __restrict__ gup4,
        const float4* __restrict__ dwn4, const float4* __restrict__ sgw4,
        const float4* __restrict__ suw4, const float4* __restrict__ sdw4,
        float* __restrict__ out, int out_size) {
    extern __shared__ char smc[];
    uint32_t sb = smem_u32(smc);
    __shared__ int ents[128];
    const int tid = threadIdx.x, lane = tid & 31, w = tid >> 5;
    const int g = lane >> 2, c = lane & 3;
    const uint32_t lmo = ((lane & 15) * RS + (lane >> 4) * 8) * 2;

    // ======================= ROUTER =======================
    if (blockIdx.x < RTRB) {
        float* hs = (float*)smc;
        float* logits = (float*)(smc + HDIM * 4);
        for (int rep = 0; rep < NTOK / RTRB; rep++) {
            int n = blockIdx.x + rep * RTRB;
            __syncthreads();
            if (tid < HDIM / 4) ((float4*)hs)[tid] = ((const float4*)(hf + (size_t)n * HDIM))[tid];
            __syncthreads();
            for (int e = w; e < NEXP + 1; e += 16) {
                const float* wr = (e < NEXP) ? (rw + (size_t)e * HDIM) : egw;
                float s = 0.f;
                for (int i = lane; i < HDIM; i += 32) s += hs[i] * wr[i];
                for (int o = 16; o > 0; o >>= 1) s += __shfl_down_sync(0xffffffffu, s, o);
                if (lane == 0) logits[e] = s;
            }
            __syncthreads();
            if (tid == 0) {
                float mx = -1e30f;
                for (int e = 0; e < NEXP; e++) mx = fmaxf(mx, logits[e]);
                float p[NEXP], den = 0.f;
                for (int e = 0; e < NEXP; e++) { p[e] = expf(logits[e] - mx); den += p[e]; }
                float inv = 1.f / den;
                for (int e = 0; e < NEXP; e++) p[e] *= inv;
                int sel[TOPK]; float sv[TOPK]; float ssum = 0.f;
                for (int k = 0; k < TOPK; k++) {
                    int bi = 0; float bv = -1.f;
                    for (int e = 0; e < NEXP; e++) if (p[e] > bv) { bv = p[e]; bi = e; }
                    sel[k] = bi; sv[k] = bv; ssum += bv; p[bi] = -2.f;
                }
                float rinv = 1.f / ssum;
                for (int k = 0; k < TOPK; k++) {
                    int entry = n * TOPK + k;
                    g_topw[entry] = sv[k] * rinv;
                    int pos = atomicAdd(&g_sync.cnt[sel[k]], 1);
                    g_list[sel[k] * NTOK + pos] = entry;
                }
                g_gatesc[n] = 1.f / (1.f + expf(-logits[NEXP]));
            }
        }
        SIGNAL(&g_sync.rtr);
        return;
    }

    // ======================= CVT SEGMENTS =======================
    if (blockIdx.x < DUAL_BASE) {
        int rel = blockIdx.x - RTRB;
        if (rel < 64) {
            cvt_seg(h4, (__half2*)g_h16, N4_H, rel, 64, tid);
            SIGNAL(&g_sync.h_c);
        } else if (rel < 128) {
            int idx = rel - 64;
            size_t stride = 64 * 512, tot = 2 * N4_SGW;
            for (size_t j = (size_t)idx * 512 + tid; j < tot; j += stride) {
                const float4* s4 = (j < N4_SGW) ? sgw4 : suw4;
                __half2* d2 = (j < N4_SGW) ? (__half2*)g_sgw16 : (__half2*)g_suw16;
                size_t o = (j < N4_SGW) ? j : j - N4_SGW;
                float4 v = s4[o];
                d2[2 * o]     = __floats2half2_rn(v.x, v.y);
                d2[2 * o + 1] = __floats2half2_rn(v.z, v.w);
            }
            SIGNAL(&g_sync.sh_c);
        } else if (rel < 640) {
            int e = (rel - 128) >> 5, idx = (rel - 128) & 31;
            cvt_seg(gup4 + (size_t)e * N4_GUP_E, (__half2*)(g_gup16 + (size_t)e * N4_GUP_E * 4),
                    N4_GUP_E, idx, 32, tid);
            SIGNAL(&g_sync.gup_c[e]);
        } else if (rel < 768) {
            int e = (rel - 640) >> 3, idx = (rel - 640) & 7;
            cvt_seg(dwn4 + (size_t)e * N4_DWN_E, (__half2*)(g_dwn16 + (size_t)e * N4_DWN_E * 4),
                    N4_DWN_E, idx, 8, tid);
            SIGNAL(&g_sync.dwn_c[e]);
        } else if (rel < 800) {
            cvt_seg(sdw4, (__half2*)g_sdw16, N4_SDW, rel - 768, 32, tid);
            SIGNAL(&g_sync.sdw_c);
        } else {
            int idx = rel - 800;
            size_t stride = 64 * 512;
            for (size_t j = (size_t)idx * 512 + tid; j < N4_OUT; j += stride)
                ((float4*)out)[j] = make_float4(0.f, 0.f, 0.f, 0.f);
            if (idx == 0 && tid == 0)
                for (int k = NTOK * HDIM; k < out_size; k++) out[k] = (float)NEXP;  // aux = E
            SIGNAL(&g_sync.out_c);
        }
        return;
    }

    // ======================= DUAL PATH =======================
    if (blockIdx.x < SGL_BASE) {
        const int bid = blockIdx.x - DUAL_BASE;
        const bool isSh = (bid < DUAL_SH_BLKS);
        const int wm = w & 3, wn = w >> 2;
        int bx, by, e = 0, cnt = 0, m0 = 0, row0 = 0;
        if (isSh) {
            bx = bid & 15; by = bid >> 4;
            row0 = by * 128;
            if (tid == 0) { SPIN(&g_sync.h_c, 64); SPIN(&g_sync.sh_c, 64); }
            __syncthreads();
        } else {
            int t = bid - DUAL_SH_BLKS;
            e = t >> 7; int r = t & 127;
            bx = r & 3; by = r >> 2;
            if (tid == 0) {
                SPIN(&g_sync.rtr, RTRB);
                SPIN(&g_sync.h_c, 64);
                SPIN(&g_sync.gup_c[e], 32);
            }
            __syncthreads();
            cnt = g_sync.cnt[e];
            m0 = by * 128;
            if (m0 >= cnt) {
                __syncthreads();
                if (tid == 0) { __threadfence(); atomicAdd(&g_sync.rdy_e[e], 1); }
                return;
            }
        }
        const int col0 = bx * 128;

        const __half* mySrc = g_h16;
        if (isSh) {
            if (tid < 128)      mySrc = g_h16   + (size_t)(row0 + tid) * HDIM;
            else if (tid < 256) mySrc = g_sgw16 + (size_t)(col0 + tid - 128) * HDIM;
            else if (tid < 384) mySrc = g_suw16 + (size_t)(col0 + tid - 256) * HDIM;
        } else {
            if (tid < 128) {
                int r = min(m0 + tid, cnt - 1);
                int entry = g_list[e * NTOK + r];
                ents[tid] = entry;
                mySrc = g_h16 + (size_t)(entry >> 2) * HDIM;
            } else if (tid < 256) {
                mySrc = g_gup16 + ((size_t)e * 2 * IDIM + col0 + tid - 128) * HDIM;
            } else if (tid < 384) {
                mySrc = g_gup16 + ((size_t)e * 2 * IDIM + IDIM + col0 + tid - 256) * HDIM;
            }
        }

        const uint32_t aB = sb + (uint32_t)(wm * 32) * 80 + lmo;
        const uint32_t gB = sb + (uint32_t)(128 + wn * 32) * 80 + lmo;
        const uint32_t uB = sb + (uint32_t)(256 + wn * 32) * 80 + lmo;

        LOADSTAGE(0, 0);  CP_COMMIT();
        LOADSTAGE(1, 32); CP_COMMIT();
        LOADSTAGE(2, 64); CP_COMMIT();

        float accg[2][4][4] = {}, accu[2][4][4] = {};
        const int NIT = HDIM / 32;
#pragma unroll 4
        for (int it = 0; it < NIT; it++) {
            CP_WAIT2();
            __syncthreads();
            if (it + 3 < NIT) LOADSTAGE((it + 3) & 3, (it + 3) * 32);
            CP_COMMIT();
            uint32_t so = (uint32_t)(it & 3) * STAGE_B;
            uint32_t af[4][4], gf[4][4], uf[4][4];   // [ks*2 + idx]
            ldm4(af[0], aB + so);        ldm4(af[1], aB + so + 1280);
            ldm4(af[2], aB + so + 32);   ldm4(af[3], aB + so + 1280 + 32);
            ldm4(gf[0], gB + so);        ldm4(gf[1], gB + so + 1280);
            ldm4(gf[2], gB + so + 32);   ldm4(gf[3], gB + so + 1280 + 32);
            ldm4(uf[0], uB + so);        ldm4(uf[1], uB + so + 1280);
            ldm4(uf[2], uB + so + 32);   ldm4(uf[3], uB + so + 1280 + 32);
#pragma unroll
            for (int ks = 0; ks < 2; ks++)
#pragma unroll
                for (int mi = 0; mi < 2; mi++)
#pragma unroll
                    for (int ni = 0; ni < 4; ni++) {
                        mma16(accg[mi][ni], af[ks * 2 + mi],
                              gf[ks * 2 + (ni >> 1)][ni & 1], gf[ks * 2 + (ni >> 1)][(ni & 1) + 2]);
                        mma16(accu[mi][ni], af[ks * 2 + mi],
                              uf[ks * 2 + (ni >> 1)][ni & 1], uf[ks * 2 + (ni >> 1)][(ni & 1) + 2]);
                    }
        }

        if (isSh) {
#pragma unroll
            for (int mi = 0; mi < 2; mi++) {
                int r = row0 + wm * 32 + mi * 16 + g;
#pragma unroll
                for (int ni = 0; ni < 4; ni++) {
                    int cc = col0 + wn * 32 + ni * 8 + 2 * c;
                    *(half2*)&g_sact16[(size_t)r * ISH + cc] =
                        __floats2half2_rn(silu_mul(accg[mi][ni][0], accu[mi][ni][0]),
                                          silu_mul(accg[mi][ni][1], accu[mi][ni][1]));
                    *(half2*)&g_sact16[(size_t)(r + 8) * ISH + cc] =
                        __floats2half2_rn(silu_mul(accg[mi][ni][2], accu[mi][ni][2]),
                                          silu_mul(accg[mi][ni][3], accu[mi][ni][3]));
                }
            }
            __syncthreads();
            if (tid == 0) { __threadfence(); atomicAdd(&g_sync.rdy_s[by], 1); }
        } else {
#pragma unroll
            for (int mi = 0; mi < 2; mi++) {
                int rl0 = wm * 32 + mi * 16 + g;
                bool v0 = (m0 + rl0) < cnt, v1 = (m0 + rl0 + 8) < cnt;
                int e0 = ents[rl0], e1 = ents[rl0 + 8];
#pragma unroll
                for (int ni = 0; ni < 4; ni++) {
                    int cc = col0 + wn * 32 + ni * 8 + 2 * c;
                    if (v0)
                        *(half2*)&g_eact16[(size_t)e0 * IDIM + cc] =
                            __floats2half2_rn(silu_mul(accg[mi][ni][0], accu[mi][ni][0]),
                                              silu_mul(accg[mi][ni][1], accu[mi][ni][1]));
                    if (v1)
                        *(half2*)&g_eact16[(size_t)e1 * IDIM + cc] =
                            __floats2half2_rn(silu_mul(accg[mi][ni][2], accu[mi][ni][2]),
                                              silu_mul(accg[mi][ni][3], accu[mi][ni][3]));
                }
            }
            __syncthreads();
            if (tid == 0) { __threadfence(); atomicAdd(&g_sync.rdy_e[e], 1); }
        }
        return;
    }

    // ======================= SINGLE PATH =======================
    {
        const int bid = blockIdx.x - SGL_BASE;
        const bool isSh = (bid < SGL_SH_BLKS);
        const int wm = w & 1, wn = w >> 1;
        int bx, by, e = 0, cnt = 0, m0 = 0, row0 = 0, NIT;
        if (isSh) {
            bx = bid & 3; by = bid >> 2;
            row0 = by * 128;
            NIT = ISH / 32;                        // 64
            if (tid == 0) {
                SPIN(&g_sync.rtr, RTRB);
                SPIN(&g_sync.sdw_c, 32);
                SPIN(&g_sync.out_c, 64);
                SPIN(&g_sync.rdy_s[by], 16);
            }
            __syncthreads();
        } else {
            int t = bid - SGL_SH_BLKS;
            e = t >> 7; int r = t & 127;
            bx = r & 3; by = r >> 2;
            NIT = IDIM / 32;                       // 16
            if (tid == 0) {
                SPIN(&g_sync.dwn_c[e], 8);
                SPIN(&g_sync.out_c, 64);
                SPIN(&g_sync.rdy_e[e], 128);
            }
            __syncthreads();
            cnt = g_sync.cnt[e];
            m0 = by * 128;
            if (m0 >= cnt) return;
        }
        const int col0 = bx * 256;

        const __half* mySrc = g_sact16;
        if (isSh) {
            if (tid < 128)      mySrc = g_sact16 + (size_t)(row0 + tid) * ISH;
            else if (tid < 384) mySrc = g_sdw16  + (size_t)(col0 + tid - 128) * ISH;
        } else {
            if (tid < 128) {
                int r = min(m0 + tid, cnt - 1);
                int entry = g_list[e * NTOK + r];
                ents[tid] = entry;
                mySrc = g_eact16 + (size_t)entry * IDIM;
            } else if (tid < 384) {
                mySrc = g_dwn16 + ((size_t)e * HDIM + col0 + tid - 128) * IDIM;
            }
        }

        const uint32_t aB = sb + (uint32_t)(wm * 64) * 80 + lmo;
        const uint32_t bB = sb + (uint32_t)(128 + wn * 32) * 80 + lmo;

        LOADSTAGE(0, 0);  CP_COMMIT();
        LOADSTAGE(1, 32); CP_COMMIT();
        LOADSTAGE(2, 64); CP_COMMIT();

        float acc[4][4][4] = {};
#pragma unroll 4
        for (int it = 0; it < NIT; it++) {
            CP_WAIT2();
            __syncthreads();
            if (it + 3 < NIT) LOADSTAGE((it + 3) & 3, (it + 3) * 32);
            CP_COMMIT();
            uint32_t so = (uint32_t)(it & 3) * STAGE_B;
            uint32_t af[8][4], bf[4][4];   // af[ks*4+mi], bf[ks*2+nq]
#pragma unroll
            for (int mi = 0; mi < 4; mi++) {
                ldm4(af[mi],     aB + so + mi * 1280);
                ldm4(af[4 + mi], aB + so + mi * 1280 + 32);
            }
#pragma unroll
            for (int nq = 0; nq < 2; nq++) {
                ldm4(bf[nq],     bB + so + nq * 1280);
                ldm4(bf[2 + nq], bB + so + nq * 1280 + 32);
            }
#pragma unroll
            for (int ks = 0; ks < 2; ks++)
#pragma unroll
                for (int mi = 0; mi < 4; mi++)
#pragma unroll
                    for (int ni = 0; ni < 4; ni++)
                        mma16(acc[mi][ni], af[ks * 4 + mi],
                              bf[ks * 2 + (ni >> 1)][ni & 1], bf[ks * 2 + (ni >> 1)][(ni & 1) + 2]);
        }

        // epilogue: XOR-1 shuffle to form 16B runs; one red.v4 per (mi,ni) per lane
#pragma unroll
        for (int mi = 0; mi < 4; mi++) {
            int rl0 = wm * 64 + mi * 16 + g;
            bool v0, v1;
            float w0, w1;
            float *d0, *d1;
            if (isSh) {
                int r = row0 + rl0;
                v0 = v1 = true;
                w0 = g_gatesc[r]; w1 = g_gatesc[r + 8];
                d0 = out + (size_t)r * HDIM;
                d1 = out + (size_t)(r + 8) * HDIM;
            } else {
                v0 = (m0 + rl0) < cnt; v1 = (m0 + rl0 + 8) < cnt;
                int e0 = ents[rl0], e1 = ents[rl0 + 8];
                w0 = v0 ? g_topw[e0] : 0.f;
                w1 = v1 ? g_topw[e1] : 0.f;
                d0 = out + (size_t)(e0 >> 2) * HDIM;
                d1 = out + (size_t)(e1 >> 2) * HDIM;
            }
#pragma unroll
            for (int ni = 0; ni < 4; ni++) {
                int cb = col0 + wn * 32 + ni * 8;
                float lx = w0 * acc[mi][ni][0], ly = w0 * acc[mi][ni][1];
                float hx = w1 * acc[mi][ni][2], hy = w1 * acc[mi][ni][3];
                float plx = __shfl_xor_sync(0xffffffffu, lx, 1);
                float ply = __shfl_xor_sync(0xffffffffu, ly, 1);
                float phx = __shfl_xor_sync(0xffffffffu, hx, 1);
                float phy = __shfl_xor_sync(0xffffffffu, hy, 1);
                if ((c & 1) == 0) {
                    if (v0) red4(d0 + cb + 2 * c, lx, ly, plx, ply);
                } else {
                    if (v1) red4(d1 + cb + 2 * (c - 1), phx, phy, hx, hy);
                }
            }
        }
    }
}

// ---------------------------------------------------------------------------
extern "C" void kernel_launch(void* const* d_in, const int* in_sizes, int n_in,
                              void* d_out, int out_size) {
    const float* h    = (const float*)d_in[0];
    const float* rw   = (const float*)d_in[1];
    const float* gup  = (const float*)d_in[2];
    const float* dwn  = (const float*)d_in[3];
    const float* sgw  = (const float*)d_in[4];
    const float* suw  = (const float*)d_in[5];
    const float* sdw  = (const float*)d_in[6];
    const float* segw = (const float*)d_in[7];
    float* out = (float*)d_out;

    cudaFuncSetAttribute(k_all, cudaFuncAttributeMaxDynamicSharedMemorySize, GEMM_SMEM);

    void* p_sync = nullptr;
    cudaGetSymbolAddress(&p_sync, g_sync);
    cudaMemsetAsync(p_sync, 0, sizeof(SyncBlk));

    k_all<<<GRID_TOT, 512, GEMM_SMEM>>>(
        h, rw, segw,
        (const float4*)h, (const float4*)gup, (const float4*)dwn,
        (const float4*)sgw, (const float4*)suw, (const float4*)sdw,
        out, out_size);
}

// round 16
// speedup vs baseline: 1.1950x; 1.1950x over previous
#include <cuda_runtime.h>
#include <cuda_fp16.h>
#include <cstdint>
#include <math.h>

#define NTOK 4096
#define HDIM 1024
#define NEXP 16
#define IDIM 512
#define ISH  2048
#define TOPK 4

#define RS        40                       // halves per smem row stride (80 bytes)
#define STAGE_B   (384 * RS * 2)           // 30720 bytes per stage (384 rows)
#define NSTAGE    4
#define GEMM_SMEM (NSTAGE * STAGE_B)       // 122880 bytes

// ---------------- fp16 operand copies + scratch (device globals) ----------------
__device__ __align__(16) __half g_h16[(size_t)NTOK * HDIM];
__device__ __align__(16) __half g_gup16[(size_t)NEXP * 2 * IDIM * HDIM];
__device__ __align__(16) __half g_dwn16[(size_t)NEXP * HDIM * IDIM];
__device__ __align__(16) __half g_sgw16[(size_t)ISH * HDIM];
__device__ __align__(16) __half g_suw16[(size_t)ISH * HDIM];
__device__ __align__(16) __half g_sdw16[(size_t)HDIM * ISH];
__device__ __align__(16) __half g_sact16[(size_t)NTOK * ISH];
__device__ __align__(16) __half g_eact16[(size_t)NTOK * TOPK * IDIM];
__device__ int   g_list[NEXP * NTOK];
__device__ float g_topw[NTOK * TOPK];
__device__ float g_gatesc[NTOK];

struct SyncBlk {
    int cnt[NEXP];    // tokens per expert (router)
    int rdy_e[NEXP];  // dual-expert blocks done per expert (target 128)
    int rdy_s[32];    // dual-shared blocks done per 128-row chunk (target 16)
};
__device__ SyncBlk g_sync;

// sizes (in float4 units)
#define N4_H    ((size_t)NTOK * HDIM / 4)
#define N4_GUP  ((size_t)NEXP * 2 * IDIM * HDIM / 4)
#define N4_DWN  ((size_t)NEXP * HDIM * IDIM / 4)
#define N4_SGW  ((size_t)ISH * HDIM / 4)
#define N4_SUW  ((size_t)ISH * HDIM / 4)
#define N4_SDW  ((size_t)HDIM * ISH / 4)
#define N4_TOT  (N4_H + N4_GUP + N4_DWN + N4_SGW + N4_SUW + N4_SDW)
#define N4_OUT  ((size_t)NTOK * HDIM / 4)

#define RTR_BLKS  4096
#define CVT_BLKS  ((int)((N4_TOT + 255) / 256))

// ---------------- helpers ----------------
__device__ __forceinline__ uint32_t smem_u32(const void* p) {
    uint32_t a;
    asm("{ .reg .u64 t; cvta.to.shared.u64 t, %1; cvt.u32.u64 %0, t; }" : "=r"(a) : "l"(p));
    return a;
}
__device__ __forceinline__ void ldm4(uint32_t* r, uint32_t addr) {
    asm volatile("ldmatrix.sync.aligned.m8n8.x4.shared.b16 {%0,%1,%2,%3}, [%4];"
                 : "=r"(r[0]), "=r"(r[1]), "=r"(r[2]), "=r"(r[3]) : "r"(addr));
}
__device__ __forceinline__ void mma16(float* d, const uint32_t* a, uint32_t b0, uint32_t b1) {
    asm volatile(
        "mma.sync.aligned.m16n8k16.row.col.f32.f16.f16.f32 "
        "{%0,%1,%2,%3}, {%4,%5,%6,%7}, {%8,%9}, {%0,%1,%2,%3};"
        : "+f"(d[0]), "+f"(d[1]), "+f"(d[2]), "+f"(d[3])
        : "r"(a[0]), "r"(a[1]), "r"(a[2]), "r"(a[3]), "r"(b0), "r"(b1));
}
__device__ __forceinline__ void cp16(uint32_t dst, const void* src) {
    asm volatile("cp.async.cg.shared.global [%0], [%1], 16;" :: "r"(dst), "l"(src));
}
#define CP_COMMIT() asm volatile("cp.async.commit_group;" ::: "memory")
#define CP_WAIT2()  asm volatile("cp.async.wait_group 2;" ::: "memory")
__device__ __forceinline__ float silu_mul(float g, float u) {
    return g / (1.f + expf(-g)) * u;
}
__device__ __forceinline__ void red4(float* p, float a, float b, float cc, float dd) {
    asm volatile("red.global.add.v4.f32 [%0], {%1,%2,%3,%4};"
                 :: "l"(p), "f"(a), "f"(b), "f"(cc), "f"(dd) : "memory");
}
__device__ __forceinline__ int ld_acq(const int* p) {
    int v;
    asm volatile("ld.global.acquire.gpu.b32 %0, [%1];" : "=r"(v) : "l"(p) : "memory");
    return v;
}

// stage fill: threads 0..383 each own one row; 64 bytes per stage
#define LOADSTAGE(st, k0)                                              \
    do {                                                               \
        if (tid < 384) {                                               \
            uint32_t _d = sb + (uint32_t)(st) * STAGE_B + (uint32_t)tid * (RS * 2); \
            const __half* _s = mySrc + (k0);                           \
            cp16(_d, _s); cp16(_d + 16, _s + 8);                       \
            cp16(_d + 32, _s + 16); cp16(_d + 48, _s + 24);            \
        }                                                              \
    } while (0)

// =====================================================================
// cvt1: router (bids [0, RTR_BLKS)) + convert ALL 6 tensors + zero out.
// g_sync pre-zeroed via cudaMemsetAsync.
// =====================================================================
__global__ void __launch_bounds__(256) cvt1_kernel(
        const float*  __restrict__ hf,   const float* __restrict__ rw,
        const float*  __restrict__ egw,
        const float4* __restrict__ h4,   const float4* __restrict__ gup4,
        const float4* __restrict__ dwn4, const float4* __restrict__ sgw4,
        const float4* __restrict__ suw4, const float4* __restrict__ sdw4,
        float* __restrict__ out, int out_size) {
    const int tid = threadIdx.x;
    if (blockIdx.x < RTR_BLKS) {
        // ---------- router: one token per block ----------
        int n = blockIdx.x, lane = tid & 31, w = tid >> 5;
        __shared__ float hs[HDIM];
        __shared__ float logits[NEXP + 1];
        const float4* hp = (const float4*)(hf + (size_t)n * HDIM);
        float4* hs4 = (float4*)hs;
        for (int i = tid; i < HDIM / 4; i += 256) hs4[i] = hp[i];
        __syncthreads();
        for (int e = w; e < NEXP + 1; e += 8) {
            const float* wr = (e < NEXP) ? (rw + (size_t)e * HDIM) : egw;
            float s = 0.f;
            for (int i = lane; i < HDIM; i += 32) s += hs[i] * wr[i];
            for (int o = 16; o > 0; o >>= 1) s += __shfl_down_sync(0xffffffffu, s, o);
            if (lane == 0) logits[e] = s;
        }
        __syncthreads();
        if (tid == 0) {
            float mx = -1e30f;
            for (int e = 0; e < NEXP; e++) mx = fmaxf(mx, logits[e]);
            float p[NEXP], den = 0.f;
            for (int e = 0; e < NEXP; e++) { p[e] = expf(logits[e] - mx); den += p[e]; }
            float inv = 1.f / den;
            for (int e = 0; e < NEXP; e++) p[e] *= inv;
            int sel[TOPK]; float sv[TOPK]; float ssum = 0.f;
            for (int k = 0; k < TOPK; k++) {
                int bi = 0; float bv = -1.f;
                for (int e = 0; e < NEXP; e++) if (p[e] > bv) { bv = p[e]; bi = e; }
                sel[k] = bi; sv[k] = bv; ssum += bv; p[bi] = -2.f;
            }
            float rinv = 1.f / ssum;
            for (int k = 0; k < TOPK; k++) {
                int entry = n * TOPK + k;
                g_topw[entry] = sv[k] * rinv;
                int pos = atomicAdd(&g_sync.cnt[sel[k]], 1);
                g_list[sel[k] * NTOK + pos] = entry;
            }
            g_gatesc[n] = 1.f / (1.f + expf(-logits[NEXP]));
        }
        return;
    }
    // ---------- conversion + output zeroing ----------
    size_t j = (size_t)(blockIdx.x - RTR_BLKS) * 256 + tid;
    if (j < N4_OUT) ((float4*)out)[j] = make_float4(0.f, 0.f, 0.f, 0.f);
    if (blockIdx.x == RTR_BLKS && tid == 0)
        for (int k = NTOK * HDIM; k < out_size; k++) out[k] = (float)NEXP;  // aux = E exactly
    if (j >= N4_TOT) return;
    const float4* src;
    __half2* dst;
    size_t o = j;
    if (o < N4_H)                    { src = h4;   dst = (__half2*)g_h16; }
    else if ((o -= N4_H) < N4_GUP)   { src = gup4; dst = (__half2*)g_gup16; }
    else if ((o -= N4_GUP) < N4_DWN) { src = dwn4; dst = (__half2*)g_dwn16; }
    else if ((o -= N4_DWN) < N4_SGW) { src = sgw4; dst = (__half2*)g_sgw16; }
    else if ((o -= N4_SGW) < N4_SUW) { src = suw4; dst = (__half2*)g_suw16; }
    else { o -= N4_SUW;                src = sdw4; dst = (__half2*)g_sdw16; }
    float4 v = src[o];
    dst[2 * o]     = __floats2half2_rn(v.x, v.y);
    dst[2 * o + 1] = __floats2half2_rn(v.z, v.w);
}

// =====================================================================
// ONE fused GEMM kernel. Block bids:
//   [0, DUAL_TOT)            : dual gate/up
//   [DUAL_TOT, +SGL_TOT)     : single down-proj (waits on ready flags)
// Inner loop: ALL chunk ldmatrix.x4 batched up front (cross-ks fragment
// registers), then the full MMA storm.
// =====================================================================

#define DUAL_SH_BLKS  ((ISH / 128) * (NTOK / 128))                // 512
#define DUAL_EX_BLKS  ((IDIM / 128) * (NTOK / 128) * NEXP)        // 2048
#define DUAL_TOT      (DUAL_SH_BLKS + DUAL_EX_BLKS)               // 2560
#define SGL_SH_BLKS   ((HDIM / 256) * (NTOK / 128))               // 128
#define SGL_EX_BLKS   ((HDIM / 256) * (NTOK / 128) * NEXP)        // 2048
#define SGL_TOT       (SGL_SH_BLKS + SGL_EX_BLKS)                 // 2176

__global__ void __launch_bounds__(512, 1) k_moe(float* __restrict__ out) {
    extern __shared__ char smc[];
    uint32_t sb = smem_u32(smc);
    __shared__ int ents[128];
    const int tid = threadIdx.x, lane = tid & 31, w = tid >> 5;
    const int g = lane >> 2, c = lane & 3;
    const uint32_t lmo = ((lane & 15) * RS + (lane >> 4) * 8) * 2;

    if (blockIdx.x < DUAL_TOT) {
        // ================= DUAL PATH: gate/up =================
        const int bid = blockIdx.x;
        const bool isSh = (bid < DUAL_SH_BLKS);
        const int wm = w & 3, wn = w >> 2;
        int bx, by, e = 0, cnt = 0, m0 = 0, row0 = 0;
        if (isSh) {
            bx = bid & 15; by = bid >> 4;
            row0 = by * 128;
        } else {
            int t = bid - DUAL_SH_BLKS;
            e = t >> 7; int r = t & 127;
            bx = r & 3; by = r >> 2;
            cnt = g_sync.cnt[e];
            m0 = by * 128;
            if (m0 >= cnt) {                      // nothing to do; still signal
                if (tid == 0) atomicAdd(&g_sync.rdy_e[e], 1);
                return;
            }
        }
        const int col0 = bx * 128;

        const __half* mySrc = g_h16;
        if (isSh) {
            if (tid < 128)      mySrc = g_h16   + (size_t)(row0 + tid) * HDIM;
            else if (tid < 256) mySrc = g_sgw16 + (size_t)(col0 + tid - 128) * HDIM;
            else if (tid < 384) mySrc = g_suw16 + (size_t)(col0 + tid - 256) * HDIM;
        } else {
            if (tid < 128) {
                int r = min(m0 + tid, cnt - 1);
                int entry = g_list[e * NTOK + r];
                ents[tid] = entry;
                mySrc = g_h16 + (size_t)(entry >> 2) * HDIM;
            } else if (tid < 256) {
                mySrc = g_gup16 + ((size_t)e * 2 * IDIM + col0 + tid - 128) * HDIM;
            } else if (tid < 384) {
                mySrc = g_gup16 + ((size_t)e * 2 * IDIM + IDIM + col0 + tid - 256) * HDIM;
            }
        }

        const uint32_t aB = sb + (uint32_t)(wm * 32) * 80 + lmo;
        const uint32_t gB = sb + (uint32_t)(128 + wn * 32) * 80 + lmo;
        const uint32_t uB = sb + (uint32_t)(256 + wn * 32) * 80 + lmo;

        LOADSTAGE(0, 0);  CP_COMMIT();
        LOADSTAGE(1, 32); CP_COMMIT();
        LOADSTAGE(2, 64); CP_COMMIT();

        float accg[2][4][4] = {}, accu[2][4][4] = {};
        const int NIT = HDIM / 32;
#pragma unroll 4
        for (int it = 0; it < NIT; it++) {
            CP_WAIT2();
            __syncthreads();
            if (it + 3 < NIT) LOADSTAGE((it + 3) & 3, (it + 3) * 32);
            CP_COMMIT();
            uint32_t so = (uint32_t)(it & 3) * STAGE_B;
            // batch ALL 12 ldmatrix for both ks up front
            uint32_t af[4][4], gf[4][4], uf[4][4];   // [ks*2 + idx]
            ldm4(af[0], aB + so);        ldm4(af[1], aB + so + 1280);
            ldm4(af[2], aB + so + 32);   ldm4(af[3], aB + so + 1280 + 32);
            ldm4(gf[0], gB + so);        ldm4(gf[1], gB + so + 1280);
            ldm4(gf[2], gB + so + 32);   ldm4(gf[3], gB + so + 1280 + 32);
            ldm4(uf[0], uB + so);        ldm4(uf[1], uB + so + 1280);
            ldm4(uf[2], uB + so + 32);   ldm4(uf[3], uB + so + 1280 + 32);
#pragma unroll
            for (int ks = 0; ks < 2; ks++)
#pragma unroll
                for (int mi = 0; mi < 2; mi++)
#pragma unroll
                    for (int ni = 0; ni < 4; ni++) {
                        mma16(accg[mi][ni], af[ks * 2 + mi],
                              gf[ks * 2 + (ni >> 1)][ni & 1], gf[ks * 2 + (ni >> 1)][(ni & 1) + 2]);
                        mma16(accu[mi][ni], af[ks * 2 + mi],
                              uf[ks * 2 + (ni >> 1)][ni & 1], uf[ks * 2 + (ni >> 1)][(ni & 1) + 2]);
                    }
        }

        if (isSh) {
#pragma unroll
            for (int mi = 0; mi < 2; mi++) {
                int r = row0 + wm * 32 + mi * 16 + g;
#pragma unroll
                for (int ni = 0; ni < 4; ni++) {
                    int cc = col0 + wn * 32 + ni * 8 + 2 * c;
                    *(half2*)&g_sact16[(size_t)r * ISH + cc] =
                        __floats2half2_rn(silu_mul(accg[mi][ni][0], accu[mi][ni][0]),
                                          silu_mul(accg[mi][ni][1], accu[mi][ni][1]));
                    *(half2*)&g_sact16[(size_t)(r + 8) * ISH + cc] =
                        __floats2half2_rn(silu_mul(accg[mi][ni][2], accu[mi][ni][2]),
                                          silu_mul(accg[mi][ni][3], accu[mi][ni][3]));
                }
            }
            __syncthreads();
            if (tid == 0) { __threadfence(); atomicAdd(&g_sync.rdy_s[by], 1); }
        } else {
#pragma unroll
            for (int mi = 0; mi < 2; mi++) {
                int rl0 = wm * 32 + mi * 16 + g;
                bool v0 = (m0 + rl0) < cnt, v1 = (m0 + rl0 + 8) < cnt;
                int e0 = ents[rl0], e1 = ents[rl0 + 8];
#pragma unroll
                for (int ni = 0; ni < 4; ni++) {
                    int cc = col0 + wn * 32 + ni * 8 + 2 * c;
                    if (v0)
                        *(half2*)&g_eact16[(size_t)e0 * IDIM + cc] =
                            __floats2half2_rn(silu_mul(accg[mi][ni][0], accu[mi][ni][0]),
                                              silu_mul(accg[mi][ni][1], accu[mi][ni][1]));
                    if (v1)
                        *(half2*)&g_eact16[(size_t)e1 * IDIM + cc] =
                            __floats2half2_rn(silu_mul(accg[mi][ni][2], accu[mi][ni][2]),
                                              silu_mul(accg[mi][ni][3], accu[mi][ni][3]));
                }
            }
            __syncthreads();
            if (tid == 0) { __threadfence(); atomicAdd(&g_sync.rdy_e[e], 1); }
        }
        return;
    }

    // ================= SINGLE PATH: down-proj =================
    {
        const int bid = blockIdx.x - DUAL_TOT;
        const bool isSh = (bid < SGL_SH_BLKS);
        const int wm = w & 1, wn = w >> 1;
        int bx, by, e = 0, cnt = 0, m0 = 0, row0 = 0, NIT;
        if (isSh) {
            bx = bid & 3; by = bid >> 2;
            row0 = by * 128;
            NIT = ISH / 32;                        // 64
            if (tid == 0) { while (ld_acq(&g_sync.rdy_s[by]) < 16) { } }
            __syncthreads();
        } else {
            int t = bid - SGL_SH_BLKS;
            e = t >> 7; int r = t & 127;
            bx = r & 3; by = r >> 2;
            cnt = g_sync.cnt[e];
            m0 = by * 128;
            if (m0 >= cnt) return;
            NIT = IDIM / 32;                       // 16
            if (tid == 0) { while (ld_acq(&g_sync.rdy_e[e]) < 128) { } }
            __syncthreads();
        }
        const int col0 = bx * 256;

        const __half* mySrc = g_sact16;
        if (isSh) {
            if (tid < 128)      mySrc = g_sact16 + (size_t)(row0 + tid) * ISH;
            else if (tid < 384) mySrc = g_sdw16  + (size_t)(col0 + tid - 128) * ISH;
        } else {
            if (tid < 128) {
                int r = min(m0 + tid, cnt - 1);
                int entry = g_list[e * NTOK + r];
                ents[tid] = entry;
                mySrc = g_eact16 + (size_t)entry * IDIM;
            } else if (tid < 384) {
                mySrc = g_dwn16 + ((size_t)e * HDIM + col0 + tid - 128) * IDIM;
            }
        }

        const uint32_t aB = sb + (uint32_t)(wm * 64) * 80 + lmo;
        const uint32_t bB = sb + (uint32_t)(128 + wn * 32) * 80 + lmo;

        LOADSTAGE(0, 0);  CP_COMMIT();
        LOADSTAGE(1, 32); CP_COMMIT();
        LOADSTAGE(2, 64); CP_COMMIT();

        float acc[4][4][4] = {};
#pragma unroll 4
        for (int it = 0; it < NIT; it++) {
            CP_WAIT2();
            __syncthreads();
            if (it + 3 < NIT) LOADSTAGE((it + 3) & 3, (it + 3) * 32);
            CP_COMMIT();
            uint32_t so = (uint32_t)(it & 3) * STAGE_B;
            // batch ALL 12 ldmatrix for both ks up front
            uint32_t af[8][4], bf[4][4];   // af[ks*4+mi], bf[ks*2+nq]
#pragma unroll
            for (int mi = 0; mi < 4; mi++) {
                ldm4(af[mi],     aB + so + mi * 1280);
                ldm4(af[4 + mi], aB + so + mi * 1280 + 32);
            }
#pragma unroll
            for (int nq = 0; nq < 2; nq++) {
                ldm4(bf[nq],     bB + so + nq * 1280);
                ldm4(bf[2 + nq], bB + so + nq * 1280 + 32);
            }
#pragma unroll
            for (int ks = 0; ks < 2; ks++)
#pragma unroll
                for (int mi = 0; mi < 4; mi++)
#pragma unroll
                    for (int ni = 0; ni < 4; ni++)
                        mma16(acc[mi][ni], af[ks * 4 + mi],
                              bf[ks * 2 + (ni >> 1)][ni & 1], bf[ks * 2 + (ni >> 1)][(ni & 1) + 2]);
        }

        // epilogue: XOR-1 shuffle to form 16B runs; one red.v4 per (mi,ni) per lane
#pragma unroll
        for (int mi = 0; mi < 4; mi++) {
            int rl0 = wm * 64 + mi * 16 + g;
            bool v0, v1;
            float w0, w1;
            float *d0, *d1;
            if (isSh) {
                int r = row0 + rl0;
                v0 = v1 = true;
                w0 = g_gatesc[r]; w1 = g_gatesc[r + 8];
                d0 = out + (size_t)r * HDIM;
                d1 = out + (size_t)(r + 8) * HDIM;
            } else {
                v0 = (m0 + rl0) < cnt; v1 = (m0 + rl0 + 8) < cnt;
                int e0 = ents[rl0], e1 = ents[rl0 + 8];
                w0 = v0 ? g_topw[e0] : 0.f;
                w1 = v1 ? g_topw[e1] : 0.f;
                d0 = out + (size_t)(e0 >> 2) * HDIM;
                d1 = out + (size_t)(e1 >> 2) * HDIM;
            }
#pragma unroll
            for (int ni = 0; ni < 4; ni++) {
                int cb = col0 + wn * 32 + ni * 8;
                float lx = w0 * acc[mi][ni][0], ly = w0 * acc[mi][ni][1];
                float hx = w1 * acc[mi][ni][2], hy = w1 * acc[mi][ni][3];
                float plx = __shfl_xor_sync(0xffffffffu, lx, 1);
                float ply = __shfl_xor_sync(0xffffffffu, ly, 1);
                float phx = __shfl_xor_sync(0xffffffffu, hx, 1);
                float phy = __shfl_xor_sync(0xffffffffu, hy, 1);
                if ((c & 1) == 0) {
                    if (v0) red4(d0 + cb + 2 * c, lx, ly, plx, ply);
                } else {
                    if (v1) red4(d1 + cb + 2 * (c - 1), phx, phy, hx, hy);
                }
            }
        }
    }
}

// ---------------------------------------------------------------------------
extern "C" void kernel_launch(void* const* d_in, const int* in_sizes, int n_in,
                              void* d_out, int out_size) {
    const float* h    = (const float*)d_in[0];
    const float* rw   = (const float*)d_in[1];
    const float* gup  = (const float*)d_in[2];
    const float* dwn  = (const float*)d_in[3];
    const float* sgw  = (const float*)d_in[4];
    const float* suw  = (const float*)d_in[5];
    const float* sdw  = (const float*)d_in[6];
    const float* segw = (const float*)d_in[7];
    float* out = (float*)d_out;

    cudaFuncSetAttribute(k_moe, cudaFuncAttributeMaxDynamicSharedMemorySize, GEMM_SMEM);

    void* p_sync = nullptr;
    cudaGetSymbolAddress(&p_sync, g_sync);
    cudaMemsetAsync(p_sync, 0, sizeof(SyncBlk));

    cvt1_kernel<<<RTR_BLKS + CVT_BLKS, 256>>>(
        h, rw, segw,
        (const float4*)h, (const float4*)gup, (const float4*)dwn,
        (const float4*)sgw, (const float4*)suw, (const float4*)sdw,
        out, out_size);

    k_moe<<<DUAL_TOT + SGL_TOT, 512, GEMM_SMEM>>>(out);
}

// round 17
// speedup vs baseline: 1.1991x; 1.0035x over previous
#include <cuda_runtime.h>
#include <cuda_fp16.h>
#include <cstdint>
#include <math.h>

#define NTOK 4096
#define HDIM 1024
#define NEXP 16
#define IDIM 512
#define ISH  2048
#define TOPK 4

#define RS        40                       // halves per smem row stride (80 bytes)
#define STAGE_B   (384 * RS * 2)           // 30720 bytes per stage (384 rows)
#define NSTAGE    4
#define GEMM_SMEM (NSTAGE * STAGE_B)       // 122880 bytes

// ---------------- fp16 operand copies + scratch (device globals) ----------------
__device__ __align__(16) __half g_h16[(size_t)NTOK * HDIM];
__device__ __align__(16) __half g_gup16[(size_t)NEXP * 2 * IDIM * HDIM];
__device__ __align__(16) __half g_dwn16[(size_t)NEXP * HDIM * IDIM];
__device__ __align__(16) __half g_sgw16[(size_t)ISH * HDIM];
__device__ __align__(16) __half g_suw16[(size_t)ISH * HDIM];
__device__ __align__(16) __half g_sdw16[(size_t)HDIM * ISH];
__device__ __align__(16) __half g_sact16[(size_t)NTOK * ISH];
__device__ __align__(16) __half g_eact16[(size_t)NTOK * TOPK * IDIM];
__device__ int   g_list[NEXP * NTOK];
__device__ float g_topw[NTOK * TOPK];
__device__ float g_gatesc[NTOK];

struct SyncBlk {
    int cnt[NEXP];    // tokens per expert (router)
    int rdy_e[NEXP];  // dual-expert blocks done per expert (target 128)
    int rdy_s[32];    // dual-shared blocks done per 128-row chunk (target 16)
};
__device__ SyncBlk g_sync;

// sizes (in float4 units); h converted by router blocks, not the sweep
#define N4_GUP  ((size_t)NEXP * 2 * IDIM * HDIM / 4)
#define N4_DWN  ((size_t)NEXP * HDIM * IDIM / 4)
#define N4_SGW  ((size_t)ISH * HDIM / 4)
#define N4_SUW  ((size_t)ISH * HDIM / 4)
#define N4_SDW  ((size_t)HDIM * ISH / 4)
#define N4_TOT  (N4_GUP + N4_DWN + N4_SGW + N4_SUW + N4_SDW)
#define N4_OUT  ((size_t)NTOK * HDIM / 4)

#define RTR_BLKS  4096
#define CVT_BLKS  ((int)((N4_TOT + 255) / 256))

// ---------------- helpers ----------------
__device__ __forceinline__ uint32_t smem_u32(const void* p) {
    uint32_t a;
    asm("{ .reg .u64 t; cvta.to.shared.u64 t, %1; cvt.u32.u64 %0, t; }" : "=r"(a) : "l"(p));
    return a;
}
__device__ __forceinline__ void ldm4(uint32_t* r, uint32_t addr) {
    asm volatile("ldmatrix.sync.aligned.m8n8.x4.shared.b16 {%0,%1,%2,%3}, [%4];"
                 : "=r"(r[0]), "=r"(r[1]), "=r"(r[2]), "=r"(r[3]) : "r"(addr));
}
__device__ __forceinline__ void mma16(float* d, const uint32_t* a, uint32_t b0, uint32_t b1) {
    asm volatile(
        "mma.sync.aligned.m16n8k16.row.col.f32.f16.f16.f32 "
        "{%0,%1,%2,%3}, {%4,%5,%6,%7}, {%8,%9}, {%0,%1,%2,%3};"
        : "+f"(d[0]), "+f"(d[1]), "+f"(d[2]), "+f"(d[3])
        : "r"(a[0]), "r"(a[1]), "r"(a[2]), "r"(a[3]), "r"(b0), "r"(b1));
}
__device__ __forceinline__ void cp16(uint32_t dst, const void* src) {
    asm volatile("cp.async.cg.shared.global [%0], [%1], 16;" :: "r"(dst), "l"(src));
}
#define CP_COMMIT() asm volatile("cp.async.commit_group;" ::: "memory")
#define CP_WAIT2()  asm volatile("cp.async.wait_group 2;" ::: "memory")
__device__ __forceinline__ float silu_mul(float g, float u) {
    return g / (1.f + expf(-g)) * u;
}
__device__ __forceinline__ void red4(float* p, float a, float b, float cc, float dd) {
    asm volatile("red.global.add.v4.f32 [%0], {%1,%2,%3,%4};"
                 :: "l"(p), "f"(a), "f"(b), "f"(cc), "f"(dd) : "memory");
}
__device__ __forceinline__ int ld_acq(const int* p) {
    int v;
    asm volatile("ld.global.acquire.gpu.b32 %0, [%1];" : "=r"(v) : "l"(p) : "memory");
    return v;
}

// stage fill: threads 0..383 each own one row; 64 bytes per stage
#define LOADSTAGE(st, k0)                                              \
    do {                                                               \
        if (tid < 384) {                                               \
            uint32_t _d = sb + (uint32_t)(st) * STAGE_B + (uint32_t)tid * (RS * 2); \
            const __half* _s = mySrc + (k0);                           \
            cp16(_d, _s); cp16(_d + 16, _s + 8);                       \
            cp16(_d + 32, _s + 16); cp16(_d + 48, _s + 24);            \
        }                                                              \
    } while (0)

// =====================================================================
// cvt1: router (bids [0, RTR_BLKS)) — ALSO writes g_h16 from its staged
// smem row — + convert gup/dwn/sgw/suw/sdw + zero out.
// g_sync pre-zeroed via cudaMemsetAsync.
// =====================================================================
__global__ void __launch_bounds__(256) cvt1_kernel(
        const float*  __restrict__ hf,   const float* __restrict__ rw,
        const float*  __restrict__ egw,
        const float4* __restrict__ gup4, const float4* __restrict__ dwn4,
        const float4* __restrict__ sgw4, const float4* __restrict__ suw4,
        const float4* __restrict__ sdw4,
        float* __restrict__ out, int out_size) {
    const int tid = threadIdx.x;
    if (blockIdx.x < RTR_BLKS) {
        // ---------- router: one token per block ----------
        int n = blockIdx.x, lane = tid & 31, w = tid >> 5;
        __shared__ float hs[HDIM];
        __shared__ float logits[NEXP + 1];
        const float4* hp = (const float4*)(hf + (size_t)n * HDIM);
        float4* hs4 = (float4*)hs;
        for (int i = tid; i < HDIM / 4; i += 256) hs4[i] = hp[i];
        __syncthreads();
        // emit fp16 copy of this token's h row (replaces the h cvt segment)
        {
            half2* d2 = (half2*)(g_h16 + (size_t)n * HDIM);
            const float2* s2 = (const float2*)hs;
            for (int i = tid; i < HDIM / 2; i += 256) {
                float2 v = s2[i];
                d2[i] = __floats2half2_rn(v.x, v.y);
            }
        }
        for (int e = w; e < NEXP + 1; e += 8) {
            const float* wr = (e < NEXP) ? (rw + (size_t)e * HDIM) : egw;
            float s = 0.f;
            for (int i = lane; i < HDIM; i += 32) s += hs[i] * wr[i];
            for (int o = 16; o > 0; o >>= 1) s += __shfl_down_sync(0xffffffffu, s, o);
            if (lane == 0) logits[e] = s;
        }
        __syncthreads();
        if (tid == 0) {
            float mx = -1e30f;
            for (int e = 0; e < NEXP; e++) mx = fmaxf(mx, logits[e]);
            float p[NEXP], den = 0.f;
            for (int e = 0; e < NEXP; e++) { p[e] = expf(logits[e] - mx); den += p[e]; }
            float inv = 1.f / den;
            for (int e = 0; e < NEXP; e++) p[e] *= inv;
            int sel[TOPK]; float sv[TOPK]; float ssum = 0.f;
            for (int k = 0; k < TOPK; k++) {
                int bi = 0; float bv = -1.f;
                for (int e = 0; e < NEXP; e++) if (p[e] > bv) { bv = p[e]; bi = e; }
                sel[k] = bi; sv[k] = bv; ssum += bv; p[bi] = -2.f;
            }
            float rinv = 1.f / ssum;
            for (int k = 0; k < TOPK; k++) {
                int entry = n * TOPK + k;
                g_topw[entry] = sv[k] * rinv;
                int pos = atomicAdd(&g_sync.cnt[sel[k]], 1);
                g_list[sel[k] * NTOK + pos] = entry;
            }
            g_gatesc[n] = 1.f / (1.f + expf(-logits[NEXP]));
        }
        return;
    }
    // ---------- conversion + output zeroing ----------
    size_t j = (size_t)(blockIdx.x - RTR_BLKS) * 256 + tid;
    if (j < N4_OUT) ((float4*)out)[j] = make_float4(0.f, 0.f, 0.f, 0.f);
    if (blockIdx.x == RTR_BLKS && tid == 0)
        for (int k = NTOK * HDIM; k < out_size; k++) out[k] = (float)NEXP;  // aux = E exactly
    if (j >= N4_TOT) return;
    const float4* src;
    __half2* dst;
    size_t o = j;
    if (o < N4_GUP)                  { src = gup4; dst = (__half2*)g_gup16; }
    else if ((o -= N4_GUP) < N4_DWN) { src = dwn4; dst = (__half2*)g_dwn16; }
    else if ((o -= N4_DWN) < N4_SGW) { src = sgw4; dst = (__half2*)g_sgw16; }
    else if ((o -= N4_SGW) < N4_SUW) { src = suw4; dst = (__half2*)g_suw16; }
    else { o -= N4_SUW;                src = sdw4; dst = (__half2*)g_sdw16; }
    float4 v = src[o];
    dst[2 * o]     = __floats2half2_rn(v.x, v.y);
    dst[2 * o + 1] = __floats2half2_rn(v.z, v.w);
}

// =====================================================================
// ONE fused GEMM kernel. Block bids:
//   [0, DUAL_TOT)            : dual gate/up
//   [DUAL_TOT, +SGL_TOT)     : single down-proj (waits on ready flags)
// =====================================================================

#define DUAL_SH_BLKS  ((ISH / 128) * (NTOK / 128))                // 512
#define DUAL_EX_BLKS  ((IDIM / 128) * (NTOK / 128) * NEXP)        // 2048
#define DUAL_TOT      (DUAL_SH_BLKS + DUAL_EX_BLKS)               // 2560
#define SGL_SH_BLKS   ((HDIM / 256) * (NTOK / 128))               // 128
#define SGL_EX_BLKS   ((HDIM / 256) * (NTOK / 128) * NEXP)        // 2048
#define SGL_TOT       (SGL_SH_BLKS + SGL_EX_BLKS)                 // 2176

__global__ void __launch_bounds__(512, 1) k_moe(float* __restrict__ out) {
    extern __shared__ char smc[];
    uint32_t sb = smem_u32(smc);
    __shared__ int ents[128];
    const int tid = threadIdx.x, lane = tid & 31, w = tid >> 5;
    const int g = lane >> 2, c = lane & 3;
    const uint32_t lmo = ((lane & 15) * RS + (lane >> 4) * 8) * 2;

    if (blockIdx.x < DUAL_TOT) {
        // ================= DUAL PATH: gate/up =================
        const int bid = blockIdx.x;
        const bool isSh = (bid < DUAL_SH_BLKS);
        const int wm = w & 3, wn = w >> 2;
        int bx, by, e = 0, cnt = 0, m0 = 0, row0 = 0;
        if (isSh) {
            bx = bid & 15; by = bid >> 4;
            row0 = by * 128;
        } else {
            int t = bid - DUAL_SH_BLKS;
            e = t >> 7; int r = t & 127;
            bx = r & 3; by = r >> 2;
            cnt = g_sync.cnt[e];
            m0 = by * 128;
            if (m0 >= cnt) {                      // nothing to do; still signal
                if (tid == 0) atomicAdd(&g_sync.rdy_e[e], 1);
                return;
            }
        }
        const int col0 = bx * 128;

        const __half* mySrc = g_h16;
        if (isSh) {
            if (tid < 128)      mySrc = g_h16   + (size_t)(row0 + tid) * HDIM;
            else if (tid < 256) mySrc = g_sgw16 + (size_t)(col0 + tid - 128) * HDIM;
            else if (tid < 384) mySrc = g_suw16 + (size_t)(col0 + tid - 256) * HDIM;
        } else {
            if (tid < 128) {
                int r = min(m0 + tid, cnt - 1);
                int entry = g_list[e * NTOK + r];
                ents[tid] = entry;
                mySrc = g_h16 + (size_t)(entry >> 2) * HDIM;
            } else if (tid < 256) {
                mySrc = g_gup16 + ((size_t)e * 2 * IDIM + col0 + tid - 128) * HDIM;
            } else if (tid < 384) {
                mySrc = g_gup16 + ((size_t)e * 2 * IDIM + IDIM + col0 + tid - 256) * HDIM;
            }
        }

        const uint32_t aB = sb + (uint32_t)(wm * 32) * 80 + lmo;
        const uint32_t gB = sb + (uint32_t)(128 + wn * 32) * 80 + lmo;
        const uint32_t uB = sb + (uint32_t)(256 + wn * 32) * 80 + lmo;

        LOADSTAGE(0, 0);  CP_COMMIT();
        LOADSTAGE(1, 32); CP_COMMIT();
        LOADSTAGE(2, 64); CP_COMMIT();

        float accg[2][4][4] = {}, accu[2][4][4] = {};
        const int NIT = HDIM / 32;
#pragma unroll 4
        for (int it = 0; it < NIT; it++) {
            CP_WAIT2();
            __syncthreads();
            if (it + 3 < NIT) LOADSTAGE((it + 3) & 3, (it + 3) * 32);
            CP_COMMIT();
            uint32_t so = (uint32_t)(it & 3) * STAGE_B;
            // batch ALL 12 ldmatrix for both ks up front
            uint32_t af[4][4], gf[4][4], uf[4][4];   // [ks*2 + idx]
            ldm4(af[0], aB + so);        ldm4(af[1], aB + so + 1280);
            ldm4(af[2], aB + so + 32);   ldm4(af[3], aB + so + 1280 + 32);
            ldm4(gf[0], gB + so);        ldm4(gf[1], gB + so + 1280);
            ldm4(gf[2], gB + so + 32);   ldm4(gf[3], gB + so + 1280 + 32);
            ldm4(uf[0], uB + so);        ldm4(uf[1], uB + so + 1280);
            ldm4(uf[2], uB + so + 32);   ldm4(uf[3], uB + so + 1280 + 32);
#pragma unroll
            for (int ks = 0; ks < 2; ks++)
#pragma unroll
                for (int mi = 0; mi < 2; mi++)
#pragma unroll
                    for (int ni = 0; ni < 4; ni++) {
                        mma16(accg[mi][ni], af[ks * 2 + mi],
                              gf[ks * 2 + (ni >> 1)][ni & 1], gf[ks * 2 + (ni >> 1)][(ni & 1) + 2]);
                        mma16(accu[mi][ni], af[ks * 2 + mi],
                              uf[ks * 2 + (ni >> 1)][ni & 1], uf[ks * 2 + (ni >> 1)][(ni & 1) + 2]);
                    }
        }

        if (isSh) {
#pragma unroll
            for (int mi = 0; mi < 2; mi++) {
                int r = row0 + wm * 32 + mi * 16 + g;
#pragma unroll
                for (int ni = 0; ni < 4; ni++) {
                    int cc = col0 + wn * 32 + ni * 8 + 2 * c;
                    *(half2*)&g_sact16[(size_t)r * ISH + cc] =
                        __floats2half2_rn(silu_mul(accg[mi][ni][0], accu[mi][ni][0]),
                                          silu_mul(accg[mi][ni][1], accu[mi][ni][1]));
                    *(half2*)&g_sact16[(size_t)(r + 8) * ISH + cc] =
                        __floats2half2_rn(silu_mul(accg[mi][ni][2], accu[mi][ni][2]),
                                          silu_mul(accg[mi][ni][3], accu[mi][ni][3]));
                }
            }
            __syncthreads();
            if (tid == 0) { __threadfence(); atomicAdd(&g_sync.rdy_s[by], 1); }
        } else {
#pragma unroll
            for (int mi = 0; mi < 2; mi++) {
                int rl0 = wm * 32 + mi * 16 + g;
                bool v0 = (m0 + rl0) < cnt, v1 = (m0 + rl0 + 8) < cnt;
                int e0 = ents[rl0], e1 = ents[rl0 + 8];
#pragma unroll
                for (int ni = 0; ni < 4; ni++) {
                    int cc = col0 + wn * 32 + ni * 8 + 2 * c;
                    if (v0)
                        *(half2*)&g_eact16[(size_t)e0 * IDIM + cc] =
                            __floats2half2_rn(silu_mul(accg[mi][ni][0], accu[mi][ni][0]),
                                              silu_mul(accg[mi][ni][1], accu[mi][ni][1]));
                    if (v1)
                        *(half2*)&g_eact16[(size_t)e1 * IDIM + cc] =
                            __floats2half2_rn(silu_mul(accg[mi][ni][2], accu[mi][ni][2]),
                                              silu_mul(accg[mi][ni][3], accu[mi][ni][3]));
                }
            }
            __syncthreads();
            if (tid == 0) { __threadfence(); atomicAdd(&g_sync.rdy_e[e], 1); }
        }
        return;
    }

    // ================= SINGLE PATH: down-proj =================
    {
        const int bid = blockIdx.x - DUAL_TOT;
        const bool isSh = (bid < SGL_SH_BLKS);
        const int wm = w & 1, wn = w >> 1;
        int bx, by, e = 0, cnt = 0, m0 = 0, row0 = 0, NIT;
        if (isSh) {
            bx = bid & 3; by = bid >> 2;
            row0 = by * 128;
            NIT = ISH / 32;                        // 64
            if (tid == 0) { while (ld_acq(&g_sync.rdy_s[by]) < 16) { } }
            __syncthreads();
        } else {
            int t = bid - SGL_SH_BLKS;
            e = t >> 7; int r = t & 127;
            bx = r & 3; by = r >> 2;
            cnt = g_sync.cnt[e];
            m0 = by * 128;
            if (m0 >= cnt) return;
            NIT = IDIM / 32;                       // 16
            if (tid == 0) { while (ld_acq(&g_sync.rdy_e[e]) < 128) { } }
            __syncthreads();
        }
        const int col0 = bx * 256;

        const __half* mySrc = g_sact16;
        if (isSh) {
            if (tid < 128)      mySrc = g_sact16 + (size_t)(row0 + tid) * ISH;
            else if (tid < 384) mySrc = g_sdw16  + (size_t)(col0 + tid - 128) * ISH;
        } else {
            if (tid < 128) {
                int r = min(m0 + tid, cnt - 1);
                int entry = g_list[e * NTOK + r];
                ents[tid] = entry;
                mySrc = g_eact16 + (size_t)entry * IDIM;
            } else if (tid < 384) {
                mySrc = g_dwn16 + ((size_t)e * HDIM + col0 + tid - 128) * IDIM;
            }
        }

        const uint32_t aB = sb + (uint32_t)(wm * 64) * 80 + lmo;
        const uint32_t bB = sb + (uint32_t)(128 + wn * 32) * 80 + lmo;

        LOADSTAGE(0, 0);  CP_COMMIT();
        LOADSTAGE(1, 32); CP_COMMIT();
        LOADSTAGE(2, 64); CP_COMMIT();

        float acc[4][4][4] = {};
#pragma unroll 4
        for (int it = 0; it < NIT; it++) {
            CP_WAIT2();
            __syncthreads();
            if (it + 3 < NIT) LOADSTAGE((it + 3) & 3, (it + 3) * 32);
            CP_COMMIT();
            uint32_t so = (uint32_t)(it & 3) * STAGE_B;
            uint32_t af[8][4], bf[4][4];   // af[ks*4+mi], bf[ks*2+nq]
#pragma unroll
            for (int mi = 0; mi < 4; mi++) {
                ldm4(af[mi],     aB + so + mi * 1280);
                ldm4(af[4 + mi], aB + so + mi * 1280 + 32);
            }
#pragma unroll
            for (int nq = 0; nq < 2; nq++) {
                ldm4(bf[nq],     bB + so + nq * 1280);
                ldm4(bf[2 + nq], bB + so + nq * 1280 + 32);
            }
#pragma unroll
            for (int ks = 0; ks < 2; ks++)
#pragma unroll
                for (int mi = 0; mi < 4; mi++)
#pragma unroll
                    for (int ni = 0; ni < 4; ni++)
                        mma16(acc[mi][ni], af[ks * 4 + mi],
                              bf[ks * 2 + (ni >> 1)][ni & 1], bf[ks * 2 + (ni >> 1)][(ni & 1) + 2]);
        }

        // epilogue: XOR-1 shuffle to form 16B runs; one red.v4 per (mi,ni) per lane
#pragma unroll
        for (int mi = 0; mi < 4; mi++) {
            int rl0 = wm * 64 + mi * 16 + g;
            bool v0, v1;
            float w0, w1;
            float *d0, *d1;
            if (isSh) {
                int r = row0 + rl0;
                v0 = v1 = true;
                w0 = g_gatesc[r]; w1 = g_gatesc[r + 8];
                d0 = out + (size_t)r * HDIM;
                d1 = out + (size_t)(r + 8) * HDIM;
            } else {
                v0 = (m0 + rl0) < cnt; v1 = (m0 + rl0 + 8) < cnt;
                int e0 = ents[rl0], e1 = ents[rl0 + 8];
                w0 = v0 ? g_topw[e0] : 0.f;
                w1 = v1 ? g_topw[e1] : 0.f;
                d0 = out + (size_t)(e0 >> 2) * HDIM;
                d1 = out + (size_t)(e1 >> 2) * HDIM;
            }
#pragma unroll
            for (int ni = 0; ni < 4; ni++) {
                int cb = col0 + wn * 32 + ni * 8;
                float lx = w0 * acc[mi][ni][0], ly = w0 * acc[mi][ni][1];
                float hx = w1 * acc[mi][ni][2], hy = w1 * acc[mi][ni][3];
                float plx = __shfl_xor_sync(0xffffffffu, lx, 1);
                float ply = __shfl_xor_sync(0xffffffffu, ly, 1);
                float phx = __shfl_xor_sync(0xffffffffu, hx, 1);
                float phy = __shfl_xor_sync(0xffffffffu, hy, 1);
                if ((c & 1) == 0) {
                    if (v0) red4(d0 + cb + 2 * c, lx, ly, plx, ply);
                } else {
                    if (v1) red4(d1 + cb + 2 * (c - 1), phx, phy, hx, hy);
                }
            }
        }
    }
}

// ---------------------------------------------------------------------------
extern "C" void kernel_launch(void* const* d_in, const int* in_sizes, int n_in,
                              void* d_out, int out_size) {
    const float* h    = (const float*)d_in[0];
    const float* rw   = (const float*)d_in[1];
    const float* gup  = (const float*)d_in[2];
    const float* dwn  = (const float*)d_in[3];
    const float* sgw  = (const float*)d_in[4];
    const float* suw  = (const float*)d_in[5];
    const float* sdw  = (const float*)d_in[6];
    const float* segw = (const float*)d_in[7];
    float* out = (float*)d_out;

    cudaFuncSetAttribute(k_moe, cudaFuncAttributeMaxDynamicSharedMemorySize, GEMM_SMEM);

    void* p_sync = nullptr;
    cudaGetSymbolAddress(&p_sync, g_sync);
    cudaMemsetAsync(p_sync, 0, sizeof(SyncBlk));

    cvt1_kernel<<<RTR_BLKS + CVT_BLKS, 256>>>(
        h, rw, segw,
        (const float4*)gup, (const float4*)dwn,
        (const float4*)sgw, (const float4*)suw, (const float4*)sdw,
        out, out_size);

    k_moe<<<DUAL_TOT + SGL_TOT, 512, GEMM_SMEM>>>(out);
}